// round 11
// baseline (speedup 1.0000x reference)
#include <cuda_runtime.h>
#include <math.h>

#define NB     4096
#define ND     4096
#define NCLS   10
#define CEB    16           // blocks in k_ce (256 rows each)

// Scratch (no allocations allowed -> __device__ globals)
__device__ float  g_r[NB];              // 1/||g_i - min_i||
__device__ int    g_cls[NB];            // argmax class
__device__ int    g_bcnt[CEB][NCLS];    // per-ce-block class counts (plain stores)
__device__ double g_cepart[CEB];        // per-ce-block CE partials (plain stores)
__device__ double g_tc[NCLS];           // sum over class of mn_i * r_i

// --------------------- CE + argmax + per-block class counts; zeroes g_tc
__global__ void __launch_bounds__(256) k_ce(
    const float* __restrict__ outputs, const int* __restrict__ y) {
    __shared__ int    cnt[NCLS];
    __shared__ double ced[8];
    int tid = threadIdx.x;
    if (tid < NCLS) cnt[tid] = 0;
    if (blockIdx.x == 0 && tid < NCLS) g_tc[tid] = 0.0;  // replay-safe re-zero
    __syncthreads();

    int row = blockIdx.x * 256 + tid;
    const float* o = outputs + row * NCLS;
    float vals[NCLS];
    float mx = o[0]; int am = 0;
    vals[0] = mx;
#pragma unroll
    for (int c = 1; c < NCLS; c++) {
        float v = o[c]; vals[c] = v;
        if (v > mx) { mx = v; am = c; }   // strict > == first max (jnp.argmax)
    }
    float e = 0.f;
#pragma unroll
    for (int c = 0; c < NCLS; c++) e += __expf(vals[c] - mx);
    double local = (double)mx + log((double)e) - (double)vals[y[row]];

    g_cls[row] = am;
    atomicAdd(&cnt[am], 1);                 // smem atomic (block-local)

#pragma unroll
    for (int off = 16; off; off >>= 1)
        local += __shfl_xor_sync(0xffffffffu, local, off);
    if ((tid & 31) == 0) ced[tid >> 5] = local;
    __syncthreads();
    if (tid < NCLS) g_bcnt[blockIdx.x][tid] = cnt[tid];
    if (tid == 0) {
        double s = 0.0;
        for (int i = 0; i < 8; i++) s += ced[i];
        g_cepart[blockIdx.x] = s;
    }
}

// ----- pass 1: per-row min/sum/sumsq + t_c ; block 0 tail writes out base
__global__ void __launch_bounds__(128) k_rowstats(
    const float* __restrict__ grad, float* __restrict__ out) {
    int row = blockIdx.x;
    int tid = threadIdx.x;
    const float4* gp = (const float4*)grad + (size_t)row * (ND / 4);

    float mn = 3.0e38f, sum = 0.f, sq = 0.f;
#pragma unroll
    for (int j = 0; j < 8; j++) {
        float4 v = gp[j * 128 + tid];
        mn  = fminf(mn, fminf(fminf(v.x, v.y), fminf(v.z, v.w)));
        sum += (v.x + v.y) + (v.z + v.w);
        sq  += (v.x * v.x + v.y * v.y) + (v.z * v.z + v.w * v.w);
    }
#pragma unroll
    for (int o = 16; o; o >>= 1) {
        mn   = fminf(mn, __shfl_xor_sync(0xffffffffu, mn, o));
        sum += __shfl_xor_sync(0xffffffffu, sum, o);
        sq  += __shfl_xor_sync(0xffffffffu, sq, o);
    }
    __shared__ float smn[4], ssum[4], ssq[4];
    int w = tid >> 5;
    if ((tid & 31) == 0) { smn[w] = mn; ssum[w] = sum; ssq[w] = sq; }
    __syncthreads();
    if (tid == 0) {
        mn = fminf(fminf(smn[0], smn[1]), fminf(smn[2], smn[3]));
        double s = (double)ssum[0] + ssum[1] + ssum[2] + ssum[3];
        double q = (double)ssq[0] + ssq[1] + ssq[2] + ssq[3];
        double mnd = (double)mn;
        // sum of (g-min)^2 ; the (max-min) scale cancels in cosine similarity
        double var = q - 2.0 * mnd * s + (double)ND * mnd * mnd;
        float rinv = (float)(1.0 / sqrt(var));
        g_r[row] = rinv;
        // t_c: 4096 REDG.F64 over 10 addrs, hidden under the stream
        atomicAdd(&g_tc[g_cls[row]], mnd * (double)rinv);
    }

    // ---- block 0 tail: loss base = ce/B + P/B + 0.5 (classsum subtracts s2/2B)
    if (blockIdx.x == 0) {
        __shared__ int    snc[NCLS];
        __shared__ double sce;
        if (tid < NCLS) {
            int acc = 0;
            for (int b = 0; b < CEB; b++) acc += g_bcnt[b][tid];
            snc[tid] = acc;
        }
        if (tid == 32) {
            double ce = 0.0;
            for (int b = 0; b < CEB; b++) ce += g_cepart[b];
            sce = ce;
        }
        __syncthreads();
        if (tid == 0) {
            double P = 0.0;
            for (int c = 0; c < NCLS; c++)
                P += 0.5 * (double)snc[c] * (double)(snc[c] - 1);
            out[0] = (float)(sce / (double)NB + P / (double)NB + 0.5);
        }
    }
}

// ----- pass 2: full class column sums + squared-norm fold, one kernel
// grid (32 stripes, NCLS) x 128: block owns ALL rows of class c for 128 cols.
// acc(thread) == S_c[col]; block folds -sum((S - t_c)^2)/(2B) into out.
__global__ void __launch_bounds__(128) k_classsum(
    const float* __restrict__ grad, float* __restrict__ out) {
    int tid = threadIdx.x;
    int c   = blockIdx.y;
    int col = blockIdx.x * 128 + tid;

    __shared__ float srw[NB];             // aliased: class ids, then weights
    __shared__ int   sidx[NB];
    int* scls = (int*)srw;

    // cache class ids (coalesced, L2-broadcast across blocks)
    for (int j = tid; j < NB; j += 128) scls[j] = g_cls[j];
    __syncthreads();

    // deterministic ballot compaction of this class's rows.
    // srw aliases scls: round k writes indices < 128(k+1); later rounds read
    // >= 128(k+1); each thread reads its scls entry before the sync. Safe.
    __shared__ int wcnt[4];
    int lane = tid & 31, wrp = tid >> 5;
    int runbase = 0;
#pragma unroll 4
    for (int k = 0; k < NB / 128; k++) {
        int r = k * 128 + tid;
        bool m = (scls[r] == c);
        unsigned bal = __ballot_sync(0xffffffffu, m);
        if (lane == 0) wcnt[wrp] = __popc(bal);
        __syncthreads();
        int pre = 0;
#pragma unroll
        for (int ww = 0; ww < 4; ww++) if (ww < wrp) pre += wcnt[ww];
        int total = wcnt[0] + wcnt[1] + wcnt[2] + wcnt[3];
        if (m) {
            int pos = runbase + pre + __popc(bal & ((1u << lane) - 1u));
            sidx[pos] = r;
            srw[pos]  = g_r[r];
        }
        runbase += total;
        __syncthreads();
    }
    int cnt = runbase;   // == n_c

    // weighted column sum: S_c[col] = sum_i r_i * grad[i][col]
    float a0 = 0.f, a1 = 0.f, a2 = 0.f, a3 = 0.f;
    float a4 = 0.f, a5 = 0.f, a6 = 0.f, a7 = 0.f;
    int i = 0;
    for (; i + 8 <= cnt; i += 8) {
        float v0 = __ldg(grad + (size_t)sidx[i + 0] * ND + col);
        float v1 = __ldg(grad + (size_t)sidx[i + 1] * ND + col);
        float v2 = __ldg(grad + (size_t)sidx[i + 2] * ND + col);
        float v3 = __ldg(grad + (size_t)sidx[i + 3] * ND + col);
        float v4 = __ldg(grad + (size_t)sidx[i + 4] * ND + col);
        float v5 = __ldg(grad + (size_t)sidx[i + 5] * ND + col);
        float v6 = __ldg(grad + (size_t)sidx[i + 6] * ND + col);
        float v7 = __ldg(grad + (size_t)sidx[i + 7] * ND + col);
        a0 = fmaf(srw[i + 0], v0, a0);
        a1 = fmaf(srw[i + 1], v1, a1);
        a2 = fmaf(srw[i + 2], v2, a2);
        a3 = fmaf(srw[i + 3], v3, a3);
        a4 = fmaf(srw[i + 4], v4, a4);
        a5 = fmaf(srw[i + 5], v5, a5);
        a6 = fmaf(srw[i + 6], v6, a6);
        a7 = fmaf(srw[i + 7], v7, a7);
    }
    for (; i < cnt; i++) {
        float v = __ldg(grad + (size_t)sidx[i] * ND + col);
        a0 = fmaf(srw[i], v, a0);
    }
    float S = ((a0 + a1) + (a2 + a3)) + ((a4 + a5) + (a6 + a7));

    // fold -(S - t_c)^2 / (2B) for this block's 128 columns into out
    double v = (double)S - g_tc[c];
    double local = v * v;
#pragma unroll
    for (int o = 16; o; o >>= 1)
        local += __shfl_xor_sync(0xffffffffu, local, o);
    __shared__ double sd[4];
    if (lane == 0) sd[wrp] = local;
    __syncthreads();
    if (tid == 0) {
        double t = sd[0] + sd[1] + sd[2] + sd[3];
        atomicAdd(out, (float)(-t / (2.0 * (double)NB)));
    }
}

extern "C" void kernel_launch(void* const* d_in, const int* in_sizes, int n_in,
                              void* d_out, int out_size) {
    (void)out_size;
    const float* outputs = nullptr;
    const float* grad    = nullptr;
    const int*   y       = nullptr;
    for (int i = 0; i < n_in; i++) {
        if      (in_sizes[i] == NB * ND)   grad    = (const float*)d_in[i];
        else if (in_sizes[i] == NB * NCLS) outputs = (const float*)d_in[i];
        else if (in_sizes[i] == NB)        y       = (const int*)d_in[i];
    }
    float* out = (float*)d_out;

    k_ce<<<CEB, 256>>>(outputs, y);
    k_rowstats<<<NB, 128>>>(grad, out);
    k_classsum<<<dim3(32, NCLS), 128>>>(grad, out);
}

// round 12
// speedup vs baseline: 1.2031x; 1.2031x over previous
#include <cuda_runtime.h>
#include <math.h>

#define NB     4096
#define ND     4096
#define NCLS   10
#define NSUB   16           // sub-chunks per class in the sorted pass
#define MAXLEN 256          // ceil(NB / NSUB) worst case (whole batch one class)
#define CEB    32           // blocks in k_ce (128 rows each)

// Scratch (no allocations allowed -> __device__ globals)
__device__ float  g_r[NB];              // 1/||g_i - min_i||
__device__ int    g_cls[NB];            // argmax class
__device__ int    g_bpos[NB];           // within-(ce-block,class) rank
__device__ int    g_bcnt[CEB][NCLS];    // per-ce-block class counts (plain stores)
__device__ double g_cepart[CEB];        // per-ce-block CE partials (plain stores)
__device__ double g_tc[NCLS];           // sum over class of mn_i * r_i
__device__ float  g_part[NCLS][NSUB][ND];  // per-(class,sub) column partials

// --------------------- CE + argmax + per-block class counts; zeroes g_tc
// 32 blocks x 128 threads, one row per thread. fp32 log-sum-exp (MUFU).
__global__ void __launch_bounds__(128) k_ce(
    const float* __restrict__ outputs, const int* __restrict__ y) {
    __shared__ int    cnt[NCLS];
    __shared__ double ced[4];
    int tid = threadIdx.x;
    if (tid < NCLS) cnt[tid] = 0;
    if (blockIdx.x == 0 && tid < NCLS) g_tc[tid] = 0.0;  // replay-safe re-zero
    __syncthreads();

    int row = blockIdx.x * 128 + tid;
    const float* o = outputs + row * NCLS;
    float vals[NCLS];
    float mx = o[0]; int am = 0;
    vals[0] = mx;
#pragma unroll
    for (int c = 1; c < NCLS; c++) {
        float v = o[c]; vals[c] = v;
        if (v > mx) { mx = v; am = c; }   // strict > == first max (jnp.argmax)
    }
    float e = 0.f;
#pragma unroll
    for (int c = 0; c < NCLS; c++) e += __expf(vals[c] - mx);
    float lse = mx + logf(e);             // fp32: ~1e-7 rel per term, ample
    double local = (double)(lse - vals[y[row]]);

    g_cls[row]  = am;
    g_bpos[row] = atomicAdd(&cnt[am], 1);   // smem atomic (block-local)

#pragma unroll
    for (int off = 16; off; off >>= 1)
        local += __shfl_xor_sync(0xffffffffu, local, off);
    if ((tid & 31) == 0) ced[tid >> 5] = local;
    __syncthreads();
    if (tid < NCLS) g_bcnt[blockIdx.x][tid] = cnt[tid];
    if (tid == 0)
        g_cepart[blockIdx.x] = ced[0] + ced[1] + ced[2] + ced[3];
}

// ---------------- pass 1: per-row min / sum / sumsq + t_c (lean streaming)
__global__ void __launch_bounds__(128) k_rowstats(const float* __restrict__ grad) {
    int row = blockIdx.x;
    int tid = threadIdx.x;
    const float4* gp = (const float4*)grad + (size_t)row * (ND / 4);

    float mn = 3.0e38f, sum = 0.f, sq = 0.f;
#pragma unroll
    for (int j = 0; j < 8; j++) {
        float4 v = gp[j * 128 + tid];
        mn  = fminf(mn, fminf(fminf(v.x, v.y), fminf(v.z, v.w)));
        sum += (v.x + v.y) + (v.z + v.w);
        sq  += (v.x * v.x + v.y * v.y) + (v.z * v.z + v.w * v.w);
    }
#pragma unroll
    for (int o = 16; o; o >>= 1) {
        mn   = fminf(mn, __shfl_xor_sync(0xffffffffu, mn, o));
        sum += __shfl_xor_sync(0xffffffffu, sum, o);
        sq  += __shfl_xor_sync(0xffffffffu, sq, o);
    }
    __shared__ float smn[4], ssum[4], ssq[4];
    int w = tid >> 5;
    if ((tid & 31) == 0) { smn[w] = mn; ssum[w] = sum; ssq[w] = sq; }
    __syncthreads();
    if (tid == 0) {
        mn = fminf(fminf(smn[0], smn[1]), fminf(smn[2], smn[3]));
        double s = (double)ssum[0] + ssum[1] + ssum[2] + ssum[3];
        double q = (double)ssq[0] + ssq[1] + ssq[2] + ssq[3];
        double mnd = (double)mn;
        // sum of (g-min)^2 ; the (max-min) scale cancels in cosine similarity
        double var = q - 2.0 * mnd * s + (double)ND * mnd * mnd;
        float rinv = (float)(1.0 / sqrt(var));
        g_r[row] = rinv;
        // t_c: 4096 REDG.F64 over 10 addrs, hidden under the stream
        atomicAdd(&g_tc[g_cls[row]], mnd * (double)rinv);
    }
}

// ------------- pass 2: class column sums; each block builds its own row list
// grid (4 stripes, NCLS, NSUB). One class per block -> 1 FFMA per element.
__global__ void __launch_bounds__(256) k_classsum(
    const float* __restrict__ grad, float* __restrict__ out) {
    int tid = threadIdx.x;
    int c   = blockIdx.y;
    int s   = blockIdx.z;
    __shared__ int   base[CEB + 1];
    __shared__ int   sidx[MAXLEN];
    __shared__ float sr[MAXLEN];
    // parallel prefix over per-ce-block counts (one warp, shfl scan)
    if (tid < CEB) {
        int v = g_bcnt[tid][c];
#pragma unroll
        for (int o = 1; o < 32; o <<= 1) {
            int nvec = __shfl_up_sync(0xffffffffu, v, o);
            if ((tid & 31) >= o) v += nvec;
        }
        base[tid + 1] = v;           // inclusive scan
        if (tid == 0) base[0] = 0;
    }
    __syncthreads();
    int n   = base[CEB];
    int len = (n + NSUB - 1) / NSUB;
    int lo  = s * len;
    int hi  = min(lo + len, n);
    int cnt = max(hi - lo, 0);

    // gather this block's row slice by scanning class ids (L2-broadcast, 16 KB)
    for (int r = tid; r < NB; r += 256) {
        if (g_cls[r] == c) {
            int p = base[r >> 7] + g_bpos[r];   // 128 rows per ce-block
            if (p >= lo && p < hi) {
                int q = p - lo;
                sidx[q] = r;
                sr[q]   = g_r[r];
            }
        }
    }
    // one designated block writes the loss base (before k_norm2 launches)
    if (blockIdx.x == 0 && c == 0 && s == 0 && tid == 0) {
        double ce = 0.0;
        for (int b = 0; b < CEB; b++) ce += g_cepart[b];
        double P = 0.0;
        for (int k = 0; k < NCLS; k++) {
            int nc = 0;
            for (int b = 0; b < CEB; b++) nc += g_bcnt[b][k];
            P += 0.5 * (double)nc * (double)(nc - 1);
        }
        // loss = ce/B + P/B + 0.5 - s2/(2B); norm2 blocks subtract s2 shares
        out[0] = (float)(ce / (double)NB + P / (double)NB + 0.5);
    }
    __syncthreads();

    int col = blockIdx.x * 1024 + tid * 4;
    float4 acc = make_float4(0.f, 0.f, 0.f, 0.f);
    int i = 0;
    for (; i + 4 <= cnt; i += 4) {
        const float4 v0 = *(const float4*)(grad + (size_t)sidx[i + 0] * ND + col);
        const float4 v1 = *(const float4*)(grad + (size_t)sidx[i + 1] * ND + col);
        const float4 v2 = *(const float4*)(grad + (size_t)sidx[i + 2] * ND + col);
        const float4 v3 = *(const float4*)(grad + (size_t)sidx[i + 3] * ND + col);
        float r0 = sr[i + 0], r1 = sr[i + 1], r2 = sr[i + 2], r3 = sr[i + 3];
        acc.x = fmaf(r0, v0.x, acc.x); acc.y = fmaf(r0, v0.y, acc.y);
        acc.z = fmaf(r0, v0.z, acc.z); acc.w = fmaf(r0, v0.w, acc.w);
        acc.x = fmaf(r1, v1.x, acc.x); acc.y = fmaf(r1, v1.y, acc.y);
        acc.z = fmaf(r1, v1.z, acc.z); acc.w = fmaf(r1, v1.w, acc.w);
        acc.x = fmaf(r2, v2.x, acc.x); acc.y = fmaf(r2, v2.y, acc.y);
        acc.z = fmaf(r2, v2.z, acc.z); acc.w = fmaf(r2, v2.w, acc.w);
        acc.x = fmaf(r3, v3.x, acc.x); acc.y = fmaf(r3, v3.y, acc.y);
        acc.z = fmaf(r3, v3.z, acc.z); acc.w = fmaf(r3, v3.w, acc.w);
    }
    for (; i < cnt; i++) {
        const float4 v = *(const float4*)(grad + (size_t)sidx[i] * ND + col);
        float r = sr[i];
        acc.x = fmaf(r, v.x, acc.x); acc.y = fmaf(r, v.y, acc.y);
        acc.z = fmaf(r, v.z, acc.z); acc.w = fmaf(r, v.w, acc.w);
    }
    // unconditional write covers empty classes/subs (no pre-zeroing needed)
    *(float4*)&g_part[c][s][col] = acc;
}

// ---- ||S_c||^2 with mean-shift (t_c); blocks fold -s2/(2B) shares into out
// grid (NCLS, 16) x 256: block covers 256 cols; subs split across 4 thread grps.
__global__ void __launch_bounds__(256) k_norm2(float* __restrict__ out) {
    int tid = threadIdx.x;
    int c   = blockIdx.x;
    int c4  = tid & 63;              // which float4-column (64 per block)
    int grp = tid >> 6;              // 4 groups x 4 subs each
    int col = blockIdx.y * 256 + c4 * 4;

    float4 p = make_float4(0.f, 0.f, 0.f, 0.f);
#pragma unroll
    for (int k = 0; k < 4; k++) {
        float4 v = *(const float4*)&g_part[c][grp * 4 + k][col];
        p.x += v.x; p.y += v.y; p.z += v.z; p.w += v.w;
    }
    __shared__ float4 sp[4][64];
    sp[grp][c4] = p;
    __syncthreads();

    __shared__ double sd[2];
    if (tid < 64) {
        float4 a = sp[0][tid], b = sp[1][tid], d = sp[2][tid], e = sp[3][tid];
        double tcv = g_tc[c];
        double x = (double)(a.x + b.x + d.x + e.x) - tcv;
        double yv = (double)(a.y + b.y + d.y + e.y) - tcv;
        double z = (double)(a.z + b.z + d.z + e.z) - tcv;
        double w = (double)(a.w + b.w + d.w + e.w) - tcv;
        double local = x * x + yv * yv + z * z + w * w;
#pragma unroll
        for (int o = 16; o; o >>= 1)
            local += __shfl_xor_sync(0xffffffffu, local, o);
        if ((tid & 31) == 0) sd[tid >> 5] = local;
    }
    __syncthreads();
    if (tid == 0)
        atomicAdd(out, (float)(-(sd[0] + sd[1]) / (2.0 * (double)NB)));
}

extern "C" void kernel_launch(void* const* d_in, const int* in_sizes, int n_in,
                              void* d_out, int out_size) {
    (void)out_size;
    const float* outputs = nullptr;
    const float* grad    = nullptr;
    const int*   y       = nullptr;
    for (int i = 0; i < n_in; i++) {
        if      (in_sizes[i] == NB * ND)   grad    = (const float*)d_in[i];
        else if (in_sizes[i] == NB * NCLS) outputs = (const float*)d_in[i];
        else if (in_sizes[i] == NB)        y       = (const int*)d_in[i];
    }
    float* out = (float*)d_out;

    k_ce<<<CEB, 128>>>(outputs, y);
    k_rowstats<<<NB, 128>>>(grad);
    k_classsum<<<dim3(4, NCLS, NSUB), 256>>>(grad, out);
    k_norm2<<<dim3(NCLS, 16), 256>>>(out);
}

// round 14
// speedup vs baseline: 1.2140x; 1.0091x over previous
#include <cuda_runtime.h>
#include <math.h>

#define NB     4096
#define ND     4096
#define NCLS   10
#define CEB    32           // blocks in k_ce (128 rows each)

// Scratch (no allocations allowed -> __device__ globals)
__device__ float  g_r[NB];              // 1/||g_i - min_i||
__device__ int    g_cls[NB];            // argmax class
__device__ int    g_bpos[NB];           // within-(ce-block,class) rank
__device__ int    g_bcnt[CEB][NCLS];    // per-ce-block class counts (plain stores)
__device__ double g_cepart[CEB];        // per-ce-block CE partials (plain stores)
__device__ double g_tc[NCLS];           // sum over class of mn_i * r_i

// --------------------- CE + argmax + per-block class counts; zeroes g_tc
// 32 blocks x 128 threads, one row per thread. fp32 log-sum-exp (MUFU).
__global__ void __launch_bounds__(128) k_ce(
    const float* __restrict__ outputs, const int* __restrict__ y) {
    __shared__ int    cnt[NCLS];
    __shared__ double ced[4];
    int tid = threadIdx.x;
    if (tid < NCLS) cnt[tid] = 0;
    if (blockIdx.x == 0 && tid < NCLS) g_tc[tid] = 0.0;  // replay-safe re-zero
    __syncthreads();

    int row = blockIdx.x * 128 + tid;
    const float* o = outputs + row * NCLS;
    float vals[NCLS];
    float mx = o[0]; int am = 0;
    vals[0] = mx;
#pragma unroll
    for (int c = 1; c < NCLS; c++) {
        float v = o[c]; vals[c] = v;
        if (v > mx) { mx = v; am = c; }   // strict > == first max (jnp.argmax)
    }
    float e = 0.f;
#pragma unroll
    for (int c = 0; c < NCLS; c++) e += __expf(vals[c] - mx);
    float lse = mx + logf(e);             // fp32: ~1e-7 rel per term, ample
    double local = (double)(lse - vals[y[row]]);

    g_cls[row]  = am;
    g_bpos[row] = atomicAdd(&cnt[am], 1);   // smem atomic (block-local)

#pragma unroll
    for (int off = 16; off; off >>= 1)
        local += __shfl_xor_sync(0xffffffffu, local, off);
    if ((tid & 31) == 0) ced[tid >> 5] = local;
    __syncthreads();
    if (tid < NCLS) g_bcnt[blockIdx.x][tid] = cnt[tid];
    if (tid == 0)
        g_cepart[blockIdx.x] = ced[0] + ced[1] + ced[2] + ced[3];
}

// ----- pass 1: per-row min/sum/sumsq + t_c ; block 0 tail writes out base
__global__ void __launch_bounds__(128) k_rowstats(
    const float* __restrict__ grad, float* __restrict__ out) {
    int row = blockIdx.x;
    int tid = threadIdx.x;
    const float4* gp = (const float4*)grad + (size_t)row * (ND / 4);

    float mn = 3.0e38f, sum = 0.f, sq = 0.f;
#pragma unroll
    for (int j = 0; j < 8; j++) {
        float4 v = gp[j * 128 + tid];
        mn  = fminf(mn, fminf(fminf(v.x, v.y), fminf(v.z, v.w)));
        sum += (v.x + v.y) + (v.z + v.w);
        sq  += (v.x * v.x + v.y * v.y) + (v.z * v.z + v.w * v.w);
    }
#pragma unroll
    for (int o = 16; o; o >>= 1) {
        mn   = fminf(mn, __shfl_xor_sync(0xffffffffu, mn, o));
        sum += __shfl_xor_sync(0xffffffffu, sum, o);
        sq  += __shfl_xor_sync(0xffffffffu, sq, o);
    }
    __shared__ float smn[4], ssum[4], ssq[4];
    int w = tid >> 5;
    if ((tid & 31) == 0) { smn[w] = mn; ssum[w] = sum; ssq[w] = sq; }
    __syncthreads();
    if (tid == 0) {
        mn = fminf(fminf(smn[0], smn[1]), fminf(smn[2], smn[3]));
        double s = (double)ssum[0] + ssum[1] + ssum[2] + ssum[3];
        double q = (double)ssq[0] + ssq[1] + ssq[2] + ssq[3];
        double mnd = (double)mn;
        // sum of (g-min)^2 ; the (max-min) scale cancels in cosine similarity
        double var = q - 2.0 * mnd * s + (double)ND * mnd * mnd;
        float rinv = (float)(1.0 / sqrt(var));
        g_r[row] = rinv;
        // t_c: 4096 REDG.F64 over 10 addrs, hidden under the stream
        atomicAdd(&g_tc[g_cls[row]], mnd * (double)rinv);
    }

    // ---- block 0 tail: loss base = ce/B + P/B + 0.5 (pass 2 subtracts s2/2B)
    if (blockIdx.x == 0) {
        __shared__ int    snc[NCLS];
        __shared__ double sce;
        if (tid < NCLS) {
            int acc = 0;
            for (int b = 0; b < CEB; b++) acc += g_bcnt[b][tid];
            snc[tid] = acc;
        }
        if (tid == 32) {
            double ce = 0.0;
            for (int b = 0; b < CEB; b++) ce += g_cepart[b];
            sce = ce;
        }
        __syncthreads();
        if (tid == 0) {
            double P = 0.0;
            for (int c = 0; c < NCLS; c++)
                P += 0.5 * (double)snc[c] * (double)(snc[c] - 1);
            out[0] = (float)(sce / (double)NB + P / (double)NB + 0.5);
        }
    }
}

// ---- pass 2 (fused): full class column sums + squared-norm fold, one kernel
// grid (32 stripes, NCLS) x 256. Block covers 128 cols (32 float4-cols) with
// 8 row-groups; smem combine yields the COMPLETE S_c[col], so the block folds
// -sum((S - t_c)^2)/(2B) into out directly. No cross-block partials.
__global__ void __launch_bounds__(256) k_fused(
    const float* __restrict__ grad, float* __restrict__ out) {
    int tid  = threadIdx.x;
    int c    = blockIdx.y;
    int c4   = tid & 31;             // float4-column within the 128-col stripe
    int grp  = tid >> 5;             // 8 row-groups (== warp id)
    int col  = blockIdx.x * 128 + c4 * 4;

    __shared__ int   base[CEB + 1];
    __shared__ int   sidx[NB];       // 16 KB
    __shared__ float sr[NB];         // 16 KB
    // parallel prefix over per-ce-block counts (one warp, shfl scan)
    if (tid < CEB) {
        int v = g_bcnt[tid][c];
#pragma unroll
        for (int o = 1; o < 32; o <<= 1) {
            int nvec = __shfl_up_sync(0xffffffffu, v, o);
            if ((tid & 31) >= o) v += nvec;
        }
        base[tid + 1] = v;           // inclusive scan
        if (tid == 0) base[0] = 0;
    }
    __syncthreads();
    int cnt = base[CEB];             // n_c

    // gather the full class row list (bpos placement; each row hits once)
    for (int r = tid; r < NB; r += 256) {
        if (g_cls[r] == c) {
            int p = base[r >> 7] + g_bpos[r];   // 128 rows per ce-block
            sidx[p] = r;
            sr[p]   = g_r[r];
        }
    }
    __syncthreads();

    // weighted column sum, rows strided by group: S_c[col] over p ≡ grp (mod 8)
    float4 acc = make_float4(0.f, 0.f, 0.f, 0.f);
    int i = grp;
    for (; i + 24 < cnt; i += 32) {
        const float4 v0 = *(const float4*)(grad + (size_t)sidx[i]      * ND + col);
        const float4 v1 = *(const float4*)(grad + (size_t)sidx[i + 8]  * ND + col);
        const float4 v2 = *(const float4*)(grad + (size_t)sidx[i + 16] * ND + col);
        const float4 v3 = *(const float4*)(grad + (size_t)sidx[i + 24] * ND + col);
        float r0 = sr[i], r1 = sr[i + 8], r2 = sr[i + 16], r3 = sr[i + 24];
        acc.x = fmaf(r0, v0.x, acc.x); acc.y = fmaf(r0, v0.y, acc.y);
        acc.z = fmaf(r0, v0.z, acc.z); acc.w = fmaf(r0, v0.w, acc.w);
        acc.x = fmaf(r1, v1.x, acc.x); acc.y = fmaf(r1, v1.y, acc.y);
        acc.z = fmaf(r1, v1.z, acc.z); acc.w = fmaf(r1, v1.w, acc.w);
        acc.x = fmaf(r2, v2.x, acc.x); acc.y = fmaf(r2, v2.y, acc.y);
        acc.z = fmaf(r2, v2.z, acc.z); acc.w = fmaf(r2, v2.w, acc.w);
        acc.x = fmaf(r3, v3.x, acc.x); acc.y = fmaf(r3, v3.y, acc.y);
        acc.z = fmaf(r3, v3.z, acc.z); acc.w = fmaf(r3, v3.w, acc.w);
    }
    for (; i < cnt; i += 8) {
        const float4 v = *(const float4*)(grad + (size_t)sidx[i] * ND + col);
        float r = sr[i];
        acc.x = fmaf(r, v.x, acc.x); acc.y = fmaf(r, v.y, acc.y);
        acc.z = fmaf(r, v.z, acc.z); acc.w = fmaf(r, v.w, acc.w);
    }

    // combine the 8 row-groups -> complete S_c for these 128 columns
    __shared__ float4 sp[8][32];
    sp[grp][c4] = acc;
    __syncthreads();

    __shared__ double sd;
    if (tid < 32) {
        float4 S = sp[0][tid];
#pragma unroll
        for (int g2 = 1; g2 < 8; g2++) {
            float4 v = sp[g2][tid];
            S.x += v.x; S.y += v.y; S.z += v.z; S.w += v.w;
        }
        double tcv = g_tc[c];
        double x = (double)S.x - tcv, yv = (double)S.y - tcv;
        double z = (double)S.z - tcv, w  = (double)S.w - tcv;
        double local = x * x + yv * yv + z * z + w * w;
#pragma unroll
        for (int o = 16; o; o >>= 1)
            local += __shfl_xor_sync(0xffffffffu, local, o);
        if (tid == 0) sd = local;
    }
    __syncthreads();
    if (tid == 0)
        atomicAdd(out, (float)(-sd / (2.0 * (double)NB)));
}

extern "C" void kernel_launch(void* const* d_in, const int* in_sizes, int n_in,
                              void* d_out, int out_size) {
    (void)out_size;
    const float* outputs = nullptr;
    const float* grad    = nullptr;
    const int*   y       = nullptr;
    for (int i = 0; i < n_in; i++) {
        if      (in_sizes[i] == NB * ND)   grad    = (const float*)d_in[i];
        else if (in_sizes[i] == NB * NCLS) outputs = (const float*)d_in[i];
        else if (in_sizes[i] == NB)        y       = (const int*)d_in[i];
    }
    float* out = (float*)d_out;

    k_ce<<<CEB, 128>>>(outputs, y);
    k_rowstats<<<NB, 128>>>(grad, out);
    k_fused<<<dim3(32, NCLS), 256>>>(grad, out);
}